// round 2
// baseline (speedup 1.0000x reference)
#include <cuda_runtime.h>
#include <math.h>

#define D       128
#define KCLUST  1024
#define BM      64      // points per CTA
#define BN      128     // clusters per tile
#define NT      256     // threads per CTA
#define XS_PITCH 65     // padded pitch, conflict-free
#define CS_PITCH 129
#define MAXN    262144

#define SMEM_BYTES ((D*XS_PITCH + D*CS_PITCH) * 4)

__device__ float g_CC[KCLUST];
__device__ int   g_yhat[MAXN];

// ---------------------------------------------------------------------------
// Prep: zero the output buffer, compute per-cluster squared norms CC[k].
// One warp per cluster: lane loads float4 at d = lane*4, warp-reduce.
// ---------------------------------------------------------------------------
__global__ void prep_kernel(const float* __restrict__ C,
                            float* __restrict__ out, int total_out) {
    int tid = blockIdx.x * blockDim.x + threadIdx.x;
    for (int i = tid; i < total_out; i += gridDim.x * blockDim.x) out[i] = 0.0f;

    int warp = tid >> 5;
    int lane = tid & 31;
    if (warp < KCLUST) {
        const float4* row = (const float4*)(C + (size_t)warp * D);
        float4 v = row[lane];
        float s = v.x * v.x + v.y * v.y + v.z * v.z + v.w * v.w;
        #pragma unroll
        for (int o = 16; o > 0; o >>= 1) s += __shfl_xor_sync(0xffffffffu, s, o);
        if (lane == 0) g_CC[warp] = s;
    }
}

// ---------------------------------------------------------------------------
// Assign: per point, argmin_k dist(x, c_k) and min dist; accumulate inertia.
// Tiled SGEMM-style: CTA owns 64 points, loops over 8 tiles of 128 clusters.
// Smem layouts are d-major with odd pitch -> conflict-free LDS/STS.
// Microtile: 4 points x 8 clusters per thread (pt = py + 16*i, cl = cx + 16*j).
// Tracks min of (CC[k] - 2*dot); XX added once at the end.
// ---------------------------------------------------------------------------
__global__ __launch_bounds__(NT, 2)
void assign_kernel(const float* __restrict__ X,
                   const float* __restrict__ C,
                   float* __restrict__ inertia) {
    extern __shared__ float smem[];
    float* Xs = smem;                 // [D][XS_PITCH] : Xs[d*65 + pt]
    float* Cs = smem + D * XS_PITCH;  // [D][CS_PITCH] : Cs[d*129 + cl]

    const int tid = threadIdx.x;
    const int cx  = tid & 15;         // cluster lane  (0..15)
    const int py  = tid >> 4;         // point lane    (0..15)
    const int n0  = blockIdx.x * BM;

    // Load X tile transposed: coalesced LDG (d contiguous per lane),
    // STS stride 65 -> conflict-free.
    for (int idx = tid; idx < BM * D; idx += NT) {
        int d = idx & (D - 1);
        int n = idx >> 7;
        Xs[d * XS_PITCH + n] = X[(size_t)(n0 + n) * D + d];
    }

    float best[4];
    int   bidx[4];
    #pragma unroll
    for (int i = 0; i < 4; i++) { best[i] = 3.4e38f; bidx[i] = 0; }

    for (int ct = 0; ct < KCLUST / BN; ct++) {
        __syncthreads();  // Cs reuse guard
        for (int idx = tid; idx < BN * D; idx += NT) {
            int d  = idx & (D - 1);
            int cl = idx >> 7;
            Cs[d * CS_PITCH + cl] = C[(size_t)(ct * BN + cl) * D + d];
        }
        __syncthreads();

        float acc[4][8];
        #pragma unroll
        for (int i = 0; i < 4; i++)
            #pragma unroll
            for (int j = 0; j < 8; j++) acc[i][j] = 0.0f;

        #pragma unroll 4
        for (int d = 0; d < D; d++) {
            float xr[4], cr[8];
            #pragma unroll
            for (int i = 0; i < 4; i++) xr[i] = Xs[d * XS_PITCH + py + 16 * i];
            #pragma unroll
            for (int j = 0; j < 8; j++) cr[j] = Cs[d * CS_PITCH + cx + 16 * j];
            #pragma unroll
            for (int i = 0; i < 4; i++)
                #pragma unroll
                for (int j = 0; j < 8; j++)
                    acc[i][j] += xr[i] * cr[j];
        }

        // Fold tile into running (min, argmin) of CC - 2*dot.
        #pragma unroll
        for (int j = 0; j < 8; j++) {
            int cl = ct * BN + cx + 16 * j;
            float cc = g_CC[cl];
            #pragma unroll
            for (int i = 0; i < 4; i++) {
                float m = cc - 2.0f * acc[i][j];
                if (m < best[i] || (m == best[i] && cl < bidx[i])) {
                    best[i] = m;
                    bidx[i] = cl;
                }
            }
        }
    }

    // Cross-thread reduction: 16 cx-threads per point.
    __syncthreads();
    float* s_min = Cs;                   // [16][64]
    int*   s_idx = (int*)(Cs + 16 * 64); // [16][64]
    #pragma unroll
    for (int i = 0; i < 4; i++) {
        s_min[cx * 64 + py + 16 * i] = best[i];
        s_idx[cx * 64 + py + 16 * i] = bidx[i];
    }
    __syncthreads();

    if (tid < BM) {
        int pt = tid;
        float b  = s_min[pt];
        int   bi = s_idx[pt];
        #pragma unroll
        for (int c = 1; c < 16; c++) {
            float v  = s_min[c * 64 + pt];
            int   vi = s_idx[c * 64 + pt];
            if (v < b || (v == b && vi < bi)) { b = v; bi = vi; }
        }
        // XX from intact Xs (stride-65 reads, conflict-free across lanes)
        float xx = 0.0f;
        #pragma unroll
        for (int d = 0; d < D; d++) {
            float x = Xs[d * XS_PITCH + pt];
            xx += x * x;
        }
        float d2   = xx + b;
        float dist = sqrtf(fmaxf(d2, 0.0f));
        g_yhat[n0 + pt] = bi;
        s_min[pt] = dist;   // reuse row 0 as per-point dist scratch
    }
    __syncthreads();
    if (tid == 0) {
        float s = 0.0f;
        #pragma unroll
        for (int i = 0; i < BM; i++) s += s_min[i];
        atomicAdd(inertia, s);
    }
}

// ---------------------------------------------------------------------------
// Scatter: one warp per point. Lane handles d = lane*4 .. lane*4+3 (float4
// coalesced loads), 8 fp32 atomicAdds (RED, no return) into cluster rows.
// ---------------------------------------------------------------------------
__global__ void scatter_kernel(const float* __restrict__ X,
                               const float* __restrict__ SW,
                               float* __restrict__ wsum,
                               float* __restrict__ xwsum,
                               int N) {
    int warp = (blockIdx.x * blockDim.x + threadIdx.x) >> 5;
    int lane = threadIdx.x & 31;
    if (warp >= N) return;

    int y = g_yhat[warp];
    float4 xv = ((const float4*)(X  + (size_t)warp * D))[lane];
    float4 sv = ((const float4*)(SW + (size_t)warp * D))[lane];

    float* wd = wsum  + (size_t)y * D + lane * 4;
    float* xd = xwsum + (size_t)y * D + lane * 4;
    atomicAdd(wd + 0, sv.x);
    atomicAdd(wd + 1, sv.y);
    atomicAdd(wd + 2, sv.z);
    atomicAdd(wd + 3, sv.w);
    atomicAdd(xd + 0, xv.x * sv.x);
    atomicAdd(xd + 1, xv.y * sv.y);
    atomicAdd(xd + 2, xv.z * sv.z);
    atomicAdd(xd + 3, xv.w * sv.w);
}

// ---------------------------------------------------------------------------
// Launch: out = [inertia(1), w_sum(K*D), xw_sum(K*D)]
// ---------------------------------------------------------------------------
extern "C" void kernel_launch(void* const* d_in, const int* in_sizes, int n_in,
                              void* d_out, int out_size) {
    const float* X  = (const float*)d_in[0];
    const float* SW = (const float*)d_in[1];
    const float* C  = (const float*)d_in[2];
    float* out = (float*)d_out;

    const int N = in_sizes[0] / D;

    float* inertia = out;
    float* wsum    = out + 1;
    float* xwsum   = out + 1 + (size_t)KCLUST * D;

    cudaFuncSetAttribute(assign_kernel,
                         cudaFuncAttributeMaxDynamicSharedMemorySize,
                         SMEM_BYTES);

    // Prep: zero output + CC. Need >= 1024 warps.
    prep_kernel<<<128, 256>>>(C, out, out_size);

    // Assign: one CTA per 64 points.
    assign_kernel<<<N / BM, NT, SMEM_BYTES>>>(X, C, inertia);

    // Scatter: one warp per point.
    int warps = N;
    int blocks = (warps * 32 + 255) / 256;
    scatter_kernel<<<blocks, 256>>>(X, SW, wsum, xwsum, N);
}

// round 11
// speedup vs baseline: 2.4111x; 2.4111x over previous
#include <cuda_runtime.h>
#include <math.h>
#include <stdint.h>

#define D       128
#define KCLUST  1024
#define BM      128        // points per CTA
#define NSTAGE  8          // 8 x 128 clusters
#define NT      256
#define MAXN    262144

// smem layout (bytes)
#define SM_B0    0          // B stage buffer 0 (64KB)
#define SM_B1    65536      // B stage buffer 1 (64KB)
#define SM_A     131072     // A permuted      (64KB)
#define SM_CCOFF 196608     // CC              (4KB)
#define SMEM_TOTAL (SM_CCOFF + KCLUST * 4)

__device__ float g_CC[KCLUST];
// B in mma-fragment order: [stage][ks 0..15][nf 0..15][lane 0..31][2 floats]
__device__ __align__(16) float g_Bperm[NSTAGE * 8192 * 2];
__device__ int g_top1[MAXN];
__device__ int g_top2[MAXN];

// ---------------------------------------------------------------------------
__device__ __forceinline__ float f2tf32(float x) {
    uint32_t r;
    asm("cvt.rna.tf32.f32 %0, %1;" : "=r"(r) : "f"(x));
    return __uint_as_float(r);
}
__device__ __forceinline__ uint32_t smem_u32(const void* p) {
    return (uint32_t)__cvta_generic_to_shared(p);
}
__device__ __forceinline__ void cp_async16(uint32_t dst, const void* src) {
    asm volatile("cp.async.cg.shared.global [%0], [%1], 16;" :: "r"(dst), "l"(src));
}
#define CP_COMMIT() asm volatile("cp.async.commit_group;" ::: "memory")
#define CP_WAIT(n)  asm volatile("cp.async.wait_group %0;" :: "n"(n) : "memory")

__device__ __forceinline__ void mma_tf32(float* c, const uint32_t* a,
                                         uint32_t b0, uint32_t b1) {
    asm volatile(
        "mma.sync.aligned.m16n8k8.row.col.f32.tf32.tf32.f32 "
        "{%0,%1,%2,%3}, {%4,%5,%6,%7}, {%8,%9}, {%0,%1,%2,%3};"
        : "+f"(c[0]), "+f"(c[1]), "+f"(c[2]), "+f"(c[3])
        : "r"(a[0]), "r"(a[1]), "r"(a[2]), "r"(a[3]), "r"(b0), "r"(b1));
}

// ---------------------------------------------------------------------------
// Prep: zero output; CC[k]; build g_Bperm (tf32, fragment order).
// Launch with >= 65536 threads.
// ---------------------------------------------------------------------------
__global__ void prep_kernel(const float* __restrict__ C,
                            float* __restrict__ out, int total_out) {
    int tid  = blockIdx.x * blockDim.x + threadIdx.x;
    int nthr = gridDim.x * blockDim.x;
    for (int i = tid; i < total_out; i += nthr) out[i] = 0.0f;

    int warp = tid >> 5;
    int lane = tid & 31;
    if (warp < KCLUST) {
        const float4* row = (const float4*)(C + (size_t)warp * D);
        float4 v = row[lane];
        float s = v.x * v.x + v.y * v.y + v.z * v.z + v.w * v.w;
        #pragma unroll
        for (int o = 16; o > 0; o >>= 1) s += __shfl_xor_sync(0xffffffffu, s, o);
        if (lane == 0) g_CC[warp] = s;
    }

    // e in [0, 65536): lane | nf(4b) | ks(4b) | stage(3b)
    for (int e = tid; e < NSTAGE * 16 * 16 * 32; e += nthr) {
        int l  = e & 31;
        int nf = (e >> 5) & 15;
        int ks = (e >> 9) & 15;
        int st = e >> 13;
        int cl = st * 128 + nf * 8 + (l >> 2);
        int k0 = ks * 8 + (l & 3);
        float2 v;
        v.x = f2tf32(C[(size_t)cl * D + k0]);
        v.y = f2tf32(C[(size_t)cl * D + k0 + 4]);
        ((float2*)g_Bperm)[e] = v;
    }
}

// ---------------------------------------------------------------------------
// Assign: tf32 mma.sync GEMM, CTA = 128 points x 1024 clusters (8 stages),
// double-buffered B via cp.async, top-2 epilogue per point.
// ---------------------------------------------------------------------------
__global__ __launch_bounds__(NT, 1)
void assign_kernel(const float* __restrict__ X) {
    extern __shared__ char smem[];
    const uint32_t sbase = smem_u32(smem);
    const int tid  = threadIdx.x;
    const int lane = tid & 31;
    const int wid  = tid >> 5;
    const int mg   = wid >> 2;       // warp m-group (0..1), 64 rows each
    const int ng   = wid & 3;        // warp n-group (0..3), 32 cols each
    const int n0   = blockIdx.x * BM;
    float* cc_s = (float*)(smem + SM_CCOFF);

    // ---- stage raw X tile into SM_B0 (coalesced float4) ----
    {
        float4* raw = (float4*)(smem + SM_B0);
        #pragma unroll
        for (int j = 0; j < 16; j++) {
            int idx = tid + j * NT;            // 4096 float4
            int row = idx >> 5, c4 = idx & 31;
            raw[idx] = ((const float4*)(X + (size_t)(n0 + row) * D))[c4];
        }
    }
    for (int i = tid; i < KCLUST; i += NT) cc_s[i] = g_CC[i];
    __syncthreads();

    // ---- permute raw X -> A fragment order in SM_A (tf32) ----
    {
        const float* raw = (const float*)(smem + SM_B0);
        float4* Ap = (float4*)(smem + SM_A);
        #pragma unroll
        for (int j = 0; j < 16; j++) {
            int e   = tid + j * NT;            // [ks(4b)|mf_g(3b)|lane(5b)]
            int l   = e & 31;
            int mfg = (e >> 5) & 7;
            int ks  = e >> 8;
            int r0  = mfg * 16 + (l >> 2);
            int k0  = ks * 8 + (l & 3);
            float4 a;
            a.x = f2tf32(raw[r0 * D + k0]);
            a.y = f2tf32(raw[(r0 + 8) * D + k0]);
            a.z = f2tf32(raw[r0 * D + k0 + 4]);
            a.w = f2tf32(raw[(r0 + 8) * D + k0 + 4]);
            Ap[e] = a;
        }
    }
    __syncthreads();

    // ---- prefetch stage 0 into SM_B0 ----
    {
        const char* src = (const char*)g_Bperm;
        #pragma unroll
        for (int j = 0; j < 16; j++) {
            int c = tid + j * NT;
            cp_async16(sbase + SM_B0 + c * 16, src + (size_t)c * 16);
        }
        CP_COMMIT();
    }

    // persistent top-2 per owned row (8 rows: mf*2 + h)
    float tb1[8], tb2[8];
    int   ti1[8], ti2[8];
    #pragma unroll
    for (int i = 0; i < 8; i++) { tb1[i] = 3.4e38f; tb2[i] = 3.4e38f; ti1[i] = 0; ti2[i] = 1; }

    const float4* Ap = (const float4*)(smem + SM_A);

    for (int s = 0; s < NSTAGE; s++) {
        // prefetch next stage
        if (s + 1 < NSTAGE) {
            uint32_t bb = sbase + (((s + 1) & 1) ? SM_B1 : SM_B0);
            const char* src = (const char*)g_Bperm + (size_t)(s + 1) * 65536;
            #pragma unroll
            for (int j = 0; j < 16; j++) {
                int c = tid + j * NT;
                cp_async16(bb + c * 16, src + (size_t)c * 16);
            }
            CP_COMMIT();
            CP_WAIT(1);
        } else {
            CP_WAIT(0);
        }
        __syncthreads();

        const float2* Bb = (const float2*)(smem + ((s & 1) ? SM_B1 : SM_B0));

        float acc[4][4][4];
        #pragma unroll
        for (int mf = 0; mf < 4; mf++)
            #pragma unroll
            for (int nf = 0; nf < 4; nf++)
                #pragma unroll
                for (int r = 0; r < 4; r++) acc[mf][nf][r] = 0.0f;

        #pragma unroll
        for (int ks = 0; ks < 16; ks++) {
            float4 av[4];
            #pragma unroll
            for (int mf = 0; mf < 4; mf++)
                av[mf] = Ap[(ks * 8 + mg * 4 + mf) * 32 + lane];
            #pragma unroll
            for (int nf = 0; nf < 4; nf++) {
                float2 bv = Bb[(ks * 16 + ng * 4 + nf) * 32 + lane];
                uint32_t b0 = __float_as_uint(bv.x);
                uint32_t b1 = __float_as_uint(bv.y);
                #pragma unroll
                for (int mf = 0; mf < 4; mf++)
                    mma_tf32(acc[mf][nf], (const uint32_t*)&av[mf], b0, b1);
            }
        }

        // fold tile into top-2:  m = CC - 2*dot
        #pragma unroll
        for (int nf = 0; nf < 4; nf++) {
            int colb = s * 128 + ng * 32 + nf * 8 + 2 * (lane & 3);
            float cc0 = cc_s[colb], cc1 = cc_s[colb + 1];
            #pragma unroll
            for (int mf = 0; mf < 4; mf++) {
                #pragma unroll
                for (int h = 0; h < 2; h++) {
                    int r = mf * 2 + h;
                    float m0 = fmaf(-2.0f, acc[mf][nf][h * 2 + 0], cc0);
                    float m1 = fmaf(-2.0f, acc[mf][nf][h * 2 + 1], cc1);
                    if (m0 < tb1[r]) { tb2[r] = tb1[r]; ti2[r] = ti1[r]; tb1[r] = m0; ti1[r] = colb; }
                    else if (m0 < tb2[r]) { tb2[r] = m0; ti2[r] = colb; }
                    if (m1 < tb1[r]) { tb2[r] = tb1[r]; ti2[r] = ti1[r]; tb1[r] = m1; ti1[r] = colb + 1; }
                    else if (m1 < tb2[r]) { tb2[r] = m1; ti2[r] = colb + 1; }
                }
            }
        }
        __syncthreads();   // buffer reuse guard
    }

    // ---- cross-warp merge (stage 7 used SM_B1; SM_B0 free) ----
    float4* red = (float4*)(smem + SM_B0);   // [row 0..127][cand 0..15]
    #pragma unroll
    for (int mf = 0; mf < 4; mf++)
        #pragma unroll
        for (int h = 0; h < 2; h++) {
            int r   = mf * 2 + h;
            int row = mg * 64 + mf * 16 + h * 8 + (lane >> 2);
            red[row * 16 + ng * 4 + (lane & 3)] =
                make_float4(tb1[r], tb2[r], __int_as_float(ti1[r]), __int_as_float(ti2[r]));
        }
    __syncthreads();

    if (tid < BM) {
        float b1 = 3.4e38f, b2 = 3.4e38f;
        int   i1 = 0,       i2 = 1;
        #pragma unroll
        for (int c = 0; c < 16; c++) {
            float4 v = red[tid * 16 + c];
            float cb1 = v.x, cb2 = v.y;
            int   ci1 = __float_as_int(v.z), ci2 = __float_as_int(v.w);
            if (cb1 < b1) { b2 = b1; i2 = i1; b1 = cb1; i1 = ci1; }
            else if (cb1 < b2) { b2 = cb1; i2 = ci1; }
            if (cb2 < b2) { b2 = cb2; i2 = ci2; }
        }
        g_top1[n0 + tid] = i1;
        g_top2[n0 + tid] = i2;
    }
}

// ---------------------------------------------------------------------------
// Rescore + scatter: one warp per point; exact fp32 d^2 for both candidates,
// pick winner, inertia, 8 RED atomics per lane.
// ---------------------------------------------------------------------------
__global__ __launch_bounds__(256)
void rescore_scatter(const float* __restrict__ X,
                     const float* __restrict__ SW,
                     const float* __restrict__ C,
                     float* __restrict__ out) {
    __shared__ float sred[8];
    const int wid  = threadIdx.x >> 5;
    const int lane = threadIdx.x & 31;
    const int p    = blockIdx.x * 8 + wid;

    int i1 = g_top1[p];
    int i2 = g_top2[p];

    float4 x  = ((const float4*)(X  + (size_t)p  * D))[lane];
    float4 s  = ((const float4*)(SW + (size_t)p  * D))[lane];
    float4 c1 = ((const float4*)(C  + (size_t)i1 * D))[lane];
    float4 c2 = ((const float4*)(C  + (size_t)i2 * D))[lane];

    float dx, d1 = 0.0f, d2 = 0.0f;
    dx = x.x - c1.x; d1 += dx * dx;  dx = x.y - c1.y; d1 += dx * dx;
    dx = x.z - c1.z; d1 += dx * dx;  dx = x.w - c1.w; d1 += dx * dx;
    dx = x.x - c2.x; d2 += dx * dx;  dx = x.y - c2.y; d2 += dx * dx;
    dx = x.z - c2.z; d2 += dx * dx;  dx = x.w - c2.w; d2 += dx * dx;
    #pragma unroll
    for (int o = 16; o > 0; o >>= 1) {
        d1 += __shfl_xor_sync(0xffffffffu, d1, o);
        d2 += __shfl_xor_sync(0xffffffffu, d2, o);
    }

    bool take1 = (d1 < d2) || (d1 == d2 && i1 < i2);
    int   y    = take1 ? i1 : i2;
    float dmin = take1 ? d1 : d2;
    if (lane == 0) sred[wid] = sqrtf(fmaxf(dmin, 0.0f));

    float* wd = out + 1 + (size_t)y * D + lane * 4;
    float* xd = out + 1 + (size_t)KCLUST * D + (size_t)y * D + lane * 4;
    atomicAdd(wd + 0, s.x); atomicAdd(wd + 1, s.y);
    atomicAdd(wd + 2, s.z); atomicAdd(wd + 3, s.w);
    atomicAdd(xd + 0, x.x * s.x); atomicAdd(xd + 1, x.y * s.y);
    atomicAdd(xd + 2, x.z * s.z); atomicAdd(xd + 3, x.w * s.w);

    __syncthreads();
    if (threadIdx.x == 0) {
        float acc = 0.0f;
        #pragma unroll
        for (int i = 0; i < 8; i++) acc += sred[i];
        atomicAdd(out, acc);
    }
}

// ---------------------------------------------------------------------------
extern "C" void kernel_launch(void* const* d_in, const int* in_sizes, int n_in,
                              void* d_out, int out_size) {
    const float* X  = (const float*)d_in[0];
    const float* SW = (const float*)d_in[1];
    const float* C  = (const float*)d_in[2];
    float* out = (float*)d_out;
    const int N = in_sizes[0] / D;

    cudaFuncSetAttribute(assign_kernel,
                         cudaFuncAttributeMaxDynamicSharedMemorySize, SMEM_TOTAL);

    prep_kernel<<<256, 256>>>(C, out, out_size);
    assign_kernel<<<N / BM, NT, SMEM_TOTAL>>>(X);
    rescore_scatter<<<N / 8, 256>>>(X, SW, C, out);
}

// round 13
// speedup vs baseline: 3.3130x; 1.3741x over previous
#include <cuda_runtime.h>
#include <math.h>
#include <stdint.h>

#define D       128
#define KCLUST  1024
#define BM      128        // points per CTA
#define NSTAGE  8          // 8 x 128 clusters
#define NT      256
#define MAXN    262144

// smem layout (bytes)
#define SM_B0    0          // B stage buffer 0 (64KB)
#define SM_B1    65536      // B stage buffer 1 (64KB)
#define SM_A     131072     // A permuted      (64KB)
#define SM_CCOFF 196608     // CC              (4KB)
#define SMEM_TOTAL (SM_CCOFF + KCLUST * 4)

__device__ float g_CC[KCLUST];
// B in mma-fragment order: [stage][ks 0..15][nf 0..15][lane 0..31][2 floats]
__device__ __align__(16) float g_Bperm[NSTAGE * 8192 * 2];
__device__ int g_top1[MAXN];
__device__ int g_top2[MAXN];
// 16B-aligned scatter accumulator: [w_sum(K*D) | xw_sum(K*D)]
__device__ __align__(16) float g_acc[2 * KCLUST * D];

// ---------------------------------------------------------------------------
__device__ __forceinline__ float f2tf32(float x) {
    uint32_t r;
    asm("cvt.rna.tf32.f32 %0, %1;" : "=r"(r) : "f"(x));
    return __uint_as_float(r);
}
__device__ __forceinline__ uint32_t smem_u32(const void* p) {
    return (uint32_t)__cvta_generic_to_shared(p);
}
__device__ __forceinline__ void cp_async16(uint32_t dst, const void* src) {
    asm volatile("cp.async.cg.shared.global [%0], [%1], 16;" :: "r"(dst), "l"(src));
}
#define CP_COMMIT() asm volatile("cp.async.commit_group;" ::: "memory")
#define CP_WAIT(n)  asm volatile("cp.async.wait_group %0;" :: "n"(n) : "memory")

__device__ __forceinline__ void mma_tf32(float* c, const uint32_t* a,
                                         uint32_t b0, uint32_t b1) {
    asm volatile(
        "mma.sync.aligned.m16n8k8.row.col.f32.tf32.tf32.f32 "
        "{%0,%1,%2,%3}, {%4,%5,%6,%7}, {%8,%9}, {%0,%1,%2,%3};"
        : "+f"(c[0]), "+f"(c[1]), "+f"(c[2]), "+f"(c[3])
        : "r"(a[0]), "r"(a[1]), "r"(a[2]), "r"(a[3]), "r"(b0), "r"(b1));
}

// Vector fp32 reduction to global (16B-aligned destination required)
__device__ __forceinline__ void red_add_v4(float* gptr, float4 v) {
    asm volatile("red.global.add.v4.f32 [%0], {%1, %2, %3, %4};"
                 :: "l"(gptr), "f"(v.x), "f"(v.y), "f"(v.z), "f"(v.w)
                 : "memory");
}

// ---------------------------------------------------------------------------
// Prep: zero output + scratch accumulator; CC[k]; build g_Bperm.
// ---------------------------------------------------------------------------
__global__ void prep_kernel(const float* __restrict__ C,
                            float* __restrict__ out, int total_out) {
    int tid  = blockIdx.x * blockDim.x + threadIdx.x;
    int nthr = gridDim.x * blockDim.x;
    for (int i = tid; i < total_out; i += nthr) out[i] = 0.0f;
    for (int i = tid; i < 2 * KCLUST * D / 4; i += nthr)
        ((float4*)g_acc)[i] = make_float4(0.f, 0.f, 0.f, 0.f);

    int warp = tid >> 5;
    int lane = tid & 31;
    if (warp < KCLUST) {
        const float4* row = (const float4*)(C + (size_t)warp * D);
        float4 v = row[lane];
        float s = v.x * v.x + v.y * v.y + v.z * v.z + v.w * v.w;
        #pragma unroll
        for (int o = 16; o > 0; o >>= 1) s += __shfl_xor_sync(0xffffffffu, s, o);
        if (lane == 0) g_CC[warp] = s;
    }

    // e in [0, 65536): lane | nf(4b) | ks(4b) | stage(3b)
    for (int e = tid; e < NSTAGE * 16 * 16 * 32; e += nthr) {
        int l  = e & 31;
        int nf = (e >> 5) & 15;
        int ks = (e >> 9) & 15;
        int st = e >> 13;
        int cl = st * 128 + nf * 8 + (l >> 2);
        int k0 = ks * 8 + (l & 3);
        float2 v;
        v.x = f2tf32(C[(size_t)cl * D + k0]);
        v.y = f2tf32(C[(size_t)cl * D + k0 + 4]);
        ((float2*)g_Bperm)[e] = v;
    }
}

// ---------------------------------------------------------------------------
// Assign: tf32 mma.sync GEMM, CTA = 128 points x 1024 clusters (8 stages),
// double-buffered B via cp.async, top-2 epilogue per point.
// ---------------------------------------------------------------------------
__global__ __launch_bounds__(NT, 1)
void assign_kernel(const float* __restrict__ X) {
    extern __shared__ char smem[];
    const uint32_t sbase = smem_u32(smem);
    const int tid  = threadIdx.x;
    const int lane = tid & 31;
    const int wid  = tid >> 5;
    const int mg   = wid >> 2;       // warp m-group (0..1), 64 rows each
    const int ng   = wid & 3;        // warp n-group (0..3), 32 cols each
    const int n0   = blockIdx.x * BM;
    float* cc_s = (float*)(smem + SM_CCOFF);

    // ---- stage raw X tile into SM_B0 (coalesced float4) ----
    {
        float4* raw = (float4*)(smem + SM_B0);
        #pragma unroll
        for (int j = 0; j < 16; j++) {
            int idx = tid + j * NT;            // 4096 float4
            int row = idx >> 5, c4 = idx & 31;
            raw[idx] = ((const float4*)(X + (size_t)(n0 + row) * D))[c4];
        }
    }
    for (int i = tid; i < KCLUST; i += NT) cc_s[i] = g_CC[i];
    __syncthreads();

    // ---- permute raw X -> A fragment order in SM_A (tf32) ----
    {
        const float* raw = (const float*)(smem + SM_B0);
        float4* Ap = (float4*)(smem + SM_A);
        #pragma unroll
        for (int j = 0; j < 16; j++) {
            int e   = tid + j * NT;            // [ks(4b)|mf_g(3b)|lane(5b)]
            int l   = e & 31;
            int mfg = (e >> 5) & 7;
            int ks  = e >> 8;
            int r0  = mfg * 16 + (l >> 2);
            int k0  = ks * 8 + (l & 3);
            float4 a;
            a.x = f2tf32(raw[r0 * D + k0]);
            a.y = f2tf32(raw[(r0 + 8) * D + k0]);
            a.z = f2tf32(raw[r0 * D + k0 + 4]);
            a.w = f2tf32(raw[(r0 + 8) * D + k0 + 4]);
            Ap[e] = a;
        }
    }
    __syncthreads();

    // ---- prefetch stage 0 into SM_B0 ----
    {
        const char* src = (const char*)g_Bperm;
        #pragma unroll
        for (int j = 0; j < 16; j++) {
            int c = tid + j * NT;
            cp_async16(sbase + SM_B0 + c * 16, src + (size_t)c * 16);
        }
        CP_COMMIT();
    }

    // persistent top-2 per owned row (8 rows: mf*2 + h)
    float tb1[8], tb2[8];
    int   ti1[8], ti2[8];
    #pragma unroll
    for (int i = 0; i < 8; i++) { tb1[i] = 3.4e38f; tb2[i] = 3.4e38f; ti1[i] = 0; ti2[i] = 1; }

    const float4* Ap = (const float4*)(smem + SM_A);

    for (int s = 0; s < NSTAGE; s++) {
        // prefetch next stage
        if (s + 1 < NSTAGE) {
            uint32_t bb = sbase + (((s + 1) & 1) ? SM_B1 : SM_B0);
            const char* src = (const char*)g_Bperm + (size_t)(s + 1) * 65536;
            #pragma unroll
            for (int j = 0; j < 16; j++) {
                int c = tid + j * NT;
                cp_async16(bb + c * 16, src + (size_t)c * 16);
            }
            CP_COMMIT();
            CP_WAIT(1);
        } else {
            CP_WAIT(0);
        }
        __syncthreads();

        const float2* Bb = (const float2*)(smem + ((s & 1) ? SM_B1 : SM_B0));

        float acc[4][4][4];
        #pragma unroll
        for (int mf = 0; mf < 4; mf++)
            #pragma unroll
            for (int nf = 0; nf < 4; nf++)
                #pragma unroll
                for (int r = 0; r < 4; r++) acc[mf][nf][r] = 0.0f;

        #pragma unroll
        for (int ks = 0; ks < 16; ks++) {
            float4 av[4];
            #pragma unroll
            for (int mf = 0; mf < 4; mf++)
                av[mf] = Ap[(ks * 8 + mg * 4 + mf) * 32 + lane];
            #pragma unroll
            for (int nf = 0; nf < 4; nf++) {
                float2 bv = Bb[(ks * 16 + ng * 4 + nf) * 32 + lane];
                uint32_t b0 = __float_as_uint(bv.x);
                uint32_t b1 = __float_as_uint(bv.y);
                #pragma unroll
                for (int mf = 0; mf < 4; mf++)
                    mma_tf32(acc[mf][nf], (const uint32_t*)&av[mf], b0, b1);
            }
        }

        // fold tile into top-2:  m = CC - 2*dot
        #pragma unroll
        for (int nf = 0; nf < 4; nf++) {
            int colb = s * 128 + ng * 32 + nf * 8 + 2 * (lane & 3);
            float cc0 = cc_s[colb], cc1 = cc_s[colb + 1];
            #pragma unroll
            for (int mf = 0; mf < 4; mf++) {
                #pragma unroll
                for (int h = 0; h < 2; h++) {
                    int r = mf * 2 + h;
                    float m0 = fmaf(-2.0f, acc[mf][nf][h * 2 + 0], cc0);
                    float m1 = fmaf(-2.0f, acc[mf][nf][h * 2 + 1], cc1);
                    if (m0 < tb1[r]) { tb2[r] = tb1[r]; ti2[r] = ti1[r]; tb1[r] = m0; ti1[r] = colb; }
                    else if (m0 < tb2[r]) { tb2[r] = m0; ti2[r] = colb; }
                    if (m1 < tb1[r]) { tb2[r] = tb1[r]; ti2[r] = ti1[r]; tb1[r] = m1; ti1[r] = colb + 1; }
                    else if (m1 < tb2[r]) { tb2[r] = m1; ti2[r] = colb + 1; }
                }
            }
        }
        __syncthreads();   // buffer reuse guard
    }

    // ---- cross-warp merge (stage 7 used SM_B1; SM_B0 free) ----
    float4* red = (float4*)(smem + SM_B0);   // [row 0..127][cand 0..15]
    #pragma unroll
    for (int mf = 0; mf < 4; mf++)
        #pragma unroll
        for (int h = 0; h < 2; h++) {
            int r   = mf * 2 + h;
            int row = mg * 64 + mf * 16 + h * 8 + (lane >> 2);
            red[row * 16 + ng * 4 + (lane & 3)] =
                make_float4(tb1[r], tb2[r], __int_as_float(ti1[r]), __int_as_float(ti2[r]));
        }
    __syncthreads();

    if (tid < BM) {
        float b1 = 3.4e38f, b2 = 3.4e38f;
        int   i1 = 0,       i2 = 1;
        #pragma unroll
        for (int c = 0; c < 16; c++) {
            float4 v = red[tid * 16 + c];
            float cb1 = v.x, cb2 = v.y;
            int   ci1 = __float_as_int(v.z), ci2 = __float_as_int(v.w);
            if (cb1 < b1) { b2 = b1; i2 = i1; b1 = cb1; i1 = ci1; }
            else if (cb1 < b2) { b2 = cb1; i2 = ci1; }
            if (cb2 < b2) { b2 = cb2; i2 = ci2; }
        }
        g_top1[n0 + tid] = i1;
        g_top2[n0 + tid] = i2;
    }
}

// ---------------------------------------------------------------------------
// Rescore + scatter: one warp per point; exact fp32 d^2 for both candidates,
// pick winner, inertia, then 2 x red.global.add.v4.f32 into aligned scratch.
// ---------------------------------------------------------------------------
__global__ __launch_bounds__(256)
void rescore_scatter(const float* __restrict__ X,
                     const float* __restrict__ SW,
                     const float* __restrict__ C,
                     float* __restrict__ out) {
    __shared__ float sred[8];
    const int wid  = threadIdx.x >> 5;
    const int lane = threadIdx.x & 31;
    const int p    = blockIdx.x * 8 + wid;

    int i1 = g_top1[p];
    int i2 = g_top2[p];

    float4 x  = ((const float4*)(X  + (size_t)p  * D))[lane];
    float4 s  = ((const float4*)(SW + (size_t)p  * D))[lane];
    float4 c1 = ((const float4*)(C  + (size_t)i1 * D))[lane];
    float4 c2 = ((const float4*)(C  + (size_t)i2 * D))[lane];

    float dx, d1 = 0.0f, d2 = 0.0f;
    dx = x.x - c1.x; d1 += dx * dx;  dx = x.y - c1.y; d1 += dx * dx;
    dx = x.z - c1.z; d1 += dx * dx;  dx = x.w - c1.w; d1 += dx * dx;
    dx = x.x - c2.x; d2 += dx * dx;  dx = x.y - c2.y; d2 += dx * dx;
    dx = x.z - c2.z; d2 += dx * dx;  dx = x.w - c2.w; d2 += dx * dx;
    #pragma unroll
    for (int o = 16; o > 0; o >>= 1) {
        d1 += __shfl_xor_sync(0xffffffffu, d1, o);
        d2 += __shfl_xor_sync(0xffffffffu, d2, o);
    }

    bool take1 = (d1 < d2) || (d1 == d2 && i1 < i2);
    int   y    = take1 ? i1 : i2;
    float dmin = take1 ? d1 : d2;
    if (lane == 0) sred[wid] = sqrtf(fmaxf(dmin, 0.0f));

    float* wd = g_acc + (size_t)y * D + lane * 4;
    float* xd = g_acc + (size_t)KCLUST * D + (size_t)y * D + lane * 4;
    red_add_v4(wd, s);
    red_add_v4(xd, make_float4(x.x * s.x, x.y * s.y, x.z * s.z, x.w * s.w));

    __syncthreads();
    if (threadIdx.x == 0) {
        float acc = 0.0f;
        #pragma unroll
        for (int i = 0; i < 8; i++) acc += sred[i];
        atomicAdd(out, acc);
    }
}

// ---------------------------------------------------------------------------
// Tail: copy scratch accumulator into the (misaligned-by-1) output region.
// ---------------------------------------------------------------------------
__global__ void finalize_kernel(float* __restrict__ out) {
    int i = blockIdx.x * blockDim.x + threadIdx.x;
    if (i < 2 * KCLUST * D / 4) {
        float4 v = ((const float4*)g_acc)[i];
        float* o = out + 1 + i * 4;
        o[0] = v.x; o[1] = v.y; o[2] = v.z; o[3] = v.w;
    }
}

// ---------------------------------------------------------------------------
extern "C" void kernel_launch(void* const* d_in, const int* in_sizes, int n_in,
                              void* d_out, int out_size) {
    const float* X  = (const float*)d_in[0];
    const float* SW = (const float*)d_in[1];
    const float* C  = (const float*)d_in[2];
    float* out = (float*)d_out;
    const int N = in_sizes[0] / D;

    cudaFuncSetAttribute(assign_kernel,
                         cudaFuncAttributeMaxDynamicSharedMemorySize, SMEM_TOTAL);

    prep_kernel<<<256, 256>>>(C, out, out_size);
    assign_kernel<<<N / BM, NT, SMEM_TOTAL>>>(X);
    rescore_scatter<<<N / 8, 256>>>(X, SW, C, out);
    finalize_kernel<<<(2 * KCLUST * D / 4 + 255) / 256, 256>>>(out);
}

// round 14
// speedup vs baseline: 3.3976x; 1.0255x over previous
#include <cuda_runtime.h>
#include <math.h>
#include <stdint.h>

#define D       128
#define KCLUST  1024
#define BM      128        // points per CTA
#define NSTAGE  8          // 8 x 128 clusters
#define NT      256
#define MAXN    262144

// smem layout (bytes)
#define SM_B0    0          // B stage buffer 0 (64KB)
#define SM_B1    65536      // B stage buffer 1 (64KB)
#define SM_A     131072     // A permuted      (64KB)
#define SM_CCOFF 196608     // CC              (4KB)
#define SMEM_TOTAL (SM_CCOFF + KCLUST * 4)

__device__ float g_CC[KCLUST];
// B in mma-fragment order: [stage][ks 0..15][nf 0..15][lane 0..31][2 floats]
__device__ __align__(16) float g_Bperm[NSTAGE * 8192 * 2];
__device__ int g_top1[MAXN];
__device__ int g_top2[MAXN];
// 16B-aligned scatter accumulator: [w_sum(K*D) | xw_sum(K*D)]
__device__ __align__(16) float g_acc[2 * KCLUST * D];

// ---------------------------------------------------------------------------
__device__ __forceinline__ float f2tf32(float x) {
    uint32_t r;
    asm("cvt.rna.tf32.f32 %0, %1;" : "=r"(r) : "f"(x));
    return __uint_as_float(r);
}
__device__ __forceinline__ uint32_t smem_u32(const void* p) {
    return (uint32_t)__cvta_generic_to_shared(p);
}
__device__ __forceinline__ void cp_async16(uint32_t dst, const void* src) {
    asm volatile("cp.async.cg.shared.global [%0], [%1], 16;" :: "r"(dst), "l"(src));
}
#define CP_COMMIT() asm volatile("cp.async.commit_group;" ::: "memory")
#define CP_WAIT(n)  asm volatile("cp.async.wait_group %0;" :: "n"(n) : "memory")

__device__ __forceinline__ void mma_tf32(float* c, const float4& a,
                                         uint32_t b0, uint32_t b1) {
    asm volatile(
        "mma.sync.aligned.m16n8k8.row.col.f32.tf32.tf32.f32 "
        "{%0,%1,%2,%3}, {%4,%5,%6,%7}, {%8,%9}, {%0,%1,%2,%3};"
        : "+f"(c[0]), "+f"(c[1]), "+f"(c[2]), "+f"(c[3])
        : "r"(__float_as_uint(a.x)), "r"(__float_as_uint(a.y)),
          "r"(__float_as_uint(a.z)), "r"(__float_as_uint(a.w)),
          "r"(b0), "r"(b1));
}

// Vector fp32 reduction to global (16B-aligned destination required)
__device__ __forceinline__ void red_add_v4(float* gptr, float4 v) {
    asm volatile("red.global.add.v4.f32 [%0], {%1, %2, %3, %4};"
                 :: "l"(gptr), "f"(v.x), "f"(v.y), "f"(v.z), "f"(v.w)
                 : "memory");
}

// ---------------------------------------------------------------------------
// Prep: zero output + scratch accumulator; CC[k]; build g_Bperm.
// ---------------------------------------------------------------------------
__global__ void prep_kernel(const float* __restrict__ C,
                            float* __restrict__ out, int total_out) {
    int tid  = blockIdx.x * blockDim.x + threadIdx.x;
    int nthr = gridDim.x * blockDim.x;
    for (int i = tid; i < total_out; i += nthr) out[i] = 0.0f;
    for (int i = tid; i < 2 * KCLUST * D / 4; i += nthr)
        ((float4*)g_acc)[i] = make_float4(0.f, 0.f, 0.f, 0.f);

    int warp = tid >> 5;
    int lane = tid & 31;
    if (warp < KCLUST) {
        const float4* row = (const float4*)(C + (size_t)warp * D);
        float4 v = row[lane];
        float s = v.x * v.x + v.y * v.y + v.z * v.z + v.w * v.w;
        #pragma unroll
        for (int o = 16; o > 0; o >>= 1) s += __shfl_xor_sync(0xffffffffu, s, o);
        if (lane == 0) g_CC[warp] = s;
    }

    // e in [0, 65536): lane | nf(4b) | ks(4b) | stage(3b)
    for (int e = tid; e < NSTAGE * 16 * 16 * 32; e += nthr) {
        int l  = e & 31;
        int nf = (e >> 5) & 15;
        int ks = (e >> 9) & 15;
        int st = e >> 13;
        int cl = st * 128 + nf * 8 + (l >> 2);
        int k0 = ks * 8 + (l & 3);
        float2 v;
        v.x = f2tf32(C[(size_t)cl * D + k0]);
        v.y = f2tf32(C[(size_t)cl * D + k0 + 4]);
        ((float2*)g_Bperm)[e] = v;
    }
}

// ---------------------------------------------------------------------------
// Assign: tf32 mma.sync GEMM, CTA = 128 points x 1024 clusters (8 stages).
// Warp grid 4x2 (warp tile 32x64); A fragments held in REGISTERS across all
// stages (loaded once) -> per-stage LDS is B-only. Top-2 epilogue per point.
// ---------------------------------------------------------------------------
__global__ __launch_bounds__(NT, 1)
void assign_kernel(const float* __restrict__ X) {
    extern __shared__ char smem[];
    const uint32_t sbase = smem_u32(smem);
    const int tid  = threadIdx.x;
    const int lane = tid & 31;
    const int wid  = tid >> 5;
    const int rg   = wid >> 1;       // row-group (0..3), 32 rows each
    const int cg   = wid & 1;        // col-group (0..1), 64 cols each
    const int n0   = blockIdx.x * BM;
    float* cc_s = (float*)(smem + SM_CCOFF);

    // ---- stage raw X tile into SM_B0 (coalesced float4) ----
    {
        float4* raw = (float4*)(smem + SM_B0);
        #pragma unroll
        for (int j = 0; j < 16; j++) {
            int idx = tid + j * NT;            // 4096 float4
            int row = idx >> 5, c4 = idx & 31;
            raw[idx] = ((const float4*)(X + (size_t)(n0 + row) * D))[c4];
        }
    }
    for (int i = tid; i < KCLUST; i += NT) cc_s[i] = g_CC[i];
    __syncthreads();

    // ---- permute raw X -> A fragment order in SM_A (tf32) ----
    {
        const float* raw = (const float*)(smem + SM_B0);
        float4* Ap = (float4*)(smem + SM_A);
        #pragma unroll
        for (int j = 0; j < 16; j++) {
            int e   = tid + j * NT;            // [ks(4b)|mf_g(3b)|lane(5b)]
            int l   = e & 31;
            int mfg = (e >> 5) & 7;
            int ks  = e >> 8;
            int r0  = mfg * 16 + (l >> 2);
            int k0  = ks * 8 + (l & 3);
            float4 a;
            a.x = f2tf32(raw[r0 * D + k0]);
            a.y = f2tf32(raw[(r0 + 8) * D + k0]);
            a.z = f2tf32(raw[r0 * D + k0 + 4]);
            a.w = f2tf32(raw[(r0 + 8) * D + k0 + 4]);
            Ap[e] = a;
        }
    }
    __syncthreads();

    // ---- load this warp's A fragments into registers (held all kernel) ----
    float4 av[2][16];
    {
        const float4* Ap = (const float4*)(smem + SM_A);
        #pragma unroll
        for (int ks = 0; ks < 16; ks++)
            #pragma unroll
            for (int mf = 0; mf < 2; mf++)
                av[mf][ks] = Ap[(ks * 8 + rg * 2 + mf) * 32 + lane];
    }

    // ---- prefetch stage 0 into SM_B0 ----
    {
        const char* src = (const char*)g_Bperm;
        #pragma unroll
        for (int j = 0; j < 16; j++) {
            int c = tid + j * NT;
            cp_async16(sbase + SM_B0 + c * 16, src + (size_t)c * 16);
        }
        CP_COMMIT();
    }

    // persistent top-2 per owned row (4 rows: mf*2 + h)
    float tb1[4], tb2[4];
    int   ti1[4], ti2[4];
    #pragma unroll
    for (int i = 0; i < 4; i++) { tb1[i] = 3.4e38f; tb2[i] = 3.4e38f; ti1[i] = 0; ti2[i] = 1; }

    for (int s = 0; s < NSTAGE; s++) {
        // prefetch next stage
        if (s + 1 < NSTAGE) {
            uint32_t bb = sbase + (((s + 1) & 1) ? SM_B1 : SM_B0);
            const char* src = (const char*)g_Bperm + (size_t)(s + 1) * 65536;
            #pragma unroll
            for (int j = 0; j < 16; j++) {
                int c = tid + j * NT;
                cp_async16(bb + c * 16, src + (size_t)c * 16);
            }
            CP_COMMIT();
            CP_WAIT(1);
        } else {
            CP_WAIT(0);
        }
        __syncthreads();

        const float2* Bb = (const float2*)(smem + ((s & 1) ? SM_B1 : SM_B0));

        float acc[2][8][4];
        #pragma unroll
        for (int mf = 0; mf < 2; mf++)
            #pragma unroll
            for (int nf = 0; nf < 8; nf++)
                #pragma unroll
                for (int r = 0; r < 4; r++) acc[mf][nf][r] = 0.0f;

        #pragma unroll
        for (int ks = 0; ks < 16; ks++) {
            uint32_t b0[8], b1[8];
            #pragma unroll
            for (int nf = 0; nf < 8; nf++) {
                float2 bv = Bb[(ks * 16 + cg * 8 + nf) * 32 + lane];
                b0[nf] = __float_as_uint(bv.x);
                b1[nf] = __float_as_uint(bv.y);
            }
            #pragma unroll
            for (int nf = 0; nf < 8; nf++)
                #pragma unroll
                for (int mf = 0; mf < 2; mf++)
                    mma_tf32(acc[mf][nf], av[mf][ks], b0[nf], b1[nf]);
        }

        // fold tile into top-2:  m = CC - 2*dot
        #pragma unroll
        for (int nf = 0; nf < 8; nf++) {
            int colb = s * 128 + cg * 64 + nf * 8 + 2 * (lane & 3);
            float cc0 = cc_s[colb], cc1 = cc_s[colb + 1];
            #pragma unroll
            for (int mf = 0; mf < 2; mf++) {
                #pragma unroll
                for (int h = 0; h < 2; h++) {
                    int r = mf * 2 + h;
                    float m0 = fmaf(-2.0f, acc[mf][nf][h * 2 + 0], cc0);
                    float m1 = fmaf(-2.0f, acc[mf][nf][h * 2 + 1], cc1);
                    if (m0 < tb1[r]) { tb2[r] = tb1[r]; ti2[r] = ti1[r]; tb1[r] = m0; ti1[r] = colb; }
                    else if (m0 < tb2[r]) { tb2[r] = m0; ti2[r] = colb; }
                    if (m1 < tb1[r]) { tb2[r] = tb1[r]; ti2[r] = ti1[r]; tb1[r] = m1; ti1[r] = colb + 1; }
                    else if (m1 < tb2[r]) { tb2[r] = m1; ti2[r] = colb + 1; }
                }
            }
        }
        __syncthreads();   // buffer reuse guard
    }

    // ---- cross-warp merge (stage 7 used SM_B1; SM_B0 free) ----
    // per row: 2 cg-warps x 4 (lane&3) threads = 8 candidates
    float4* red = (float4*)(smem + SM_B0);   // [row 0..127][cand 0..7]
    #pragma unroll
    for (int mf = 0; mf < 2; mf++)
        #pragma unroll
        for (int h = 0; h < 2; h++) {
            int r   = mf * 2 + h;
            int row = rg * 32 + mf * 16 + h * 8 + (lane >> 2);
            red[row * 8 + cg * 4 + (lane & 3)] =
                make_float4(tb1[r], tb2[r], __int_as_float(ti1[r]), __int_as_float(ti2[r]));
        }
    __syncthreads();

    if (tid < BM) {
        float b1 = 3.4e38f, b2 = 3.4e38f;
        int   i1 = 0,       i2 = 1;
        #pragma unroll
        for (int c = 0; c < 8; c++) {
            float4 v = red[tid * 8 + c];
            float cb1 = v.x, cb2 = v.y;
            int   ci1 = __float_as_int(v.z), ci2 = __float_as_int(v.w);
            if (cb1 < b1) { b2 = b1; i2 = i1; b1 = cb1; i1 = ci1; }
            else if (cb1 < b2) { b2 = cb1; i2 = ci1; }
            if (cb2 < b2) { b2 = cb2; i2 = ci2; }
        }
        g_top1[n0 + tid] = i1;
        g_top2[n0 + tid] = i2;
    }
}

// ---------------------------------------------------------------------------
// Rescore + scatter: one warp per point; exact fp32 d^2 for both candidates,
// pick winner, inertia, then 2 x red.global.add.v4.f32 into aligned scratch.
// ---------------------------------------------------------------------------
__global__ __launch_bounds__(256)
void rescore_scatter(const float* __restrict__ X,
                     const float* __restrict__ SW,
                     const float* __restrict__ C,
                     float* __restrict__ out) {
    __shared__ float sred[8];
    const int wid  = threadIdx.x >> 5;
    const int lane = threadIdx.x & 31;
    const int p    = blockIdx.x * 8 + wid;

    int i1 = g_top1[p];
    int i2 = g_top2[p];

    float4 x  = ((const float4*)(X  + (size_t)p  * D))[lane];
    float4 s  = ((const float4*)(SW + (size_t)p  * D))[lane];
    float4 c1 = ((const float4*)(C  + (size_t)i1 * D))[lane];
    float4 c2 = ((const float4*)(C  + (size_t)i2 * D))[lane];

    float dx, d1 = 0.0f, d2 = 0.0f;
    dx = x.x - c1.x; d1 += dx * dx;  dx = x.y - c1.y; d1 += dx * dx;
    dx = x.z - c1.z; d1 += dx * dx;  dx = x.w - c1.w; d1 += dx * dx;
    dx = x.x - c2.x; d2 += dx * dx;  dx = x.y - c2.y; d2 += dx * dx;
    dx = x.z - c2.z; d2 += dx * dx;  dx = x.w - c2.w; d2 += dx * dx;
    #pragma unroll
    for (int o = 16; o > 0; o >>= 1) {
        d1 += __shfl_xor_sync(0xffffffffu, d1, o);
        d2 += __shfl_xor_sync(0xffffffffu, d2, o);
    }

    bool take1 = (d1 < d2) || (d1 == d2 && i1 < i2);
    int   y    = take1 ? i1 : i2;
    float dmin = take1 ? d1 : d2;
    if (lane == 0) sred[wid] = sqrtf(fmaxf(dmin, 0.0f));

    float* wd = g_acc + (size_t)y * D + lane * 4;
    float* xd = g_acc + (size_t)KCLUST * D + (size_t)y * D + lane * 4;
    red_add_v4(wd, s);
    red_add_v4(xd, make_float4(x.x * s.x, x.y * s.y, x.z * s.z, x.w * s.w));

    __syncthreads();
    if (threadIdx.x == 0) {
        float acc = 0.0f;
        #pragma unroll
        for (int i = 0; i < 8; i++) acc += sred[i];
        atomicAdd(out, acc);
    }
}

// ---------------------------------------------------------------------------
// Tail: copy scratch accumulator into the (misaligned-by-1) output region.
// ---------------------------------------------------------------------------
__global__ void finalize_kernel(float* __restrict__ out) {
    int i = blockIdx.x * blockDim.x + threadIdx.x;
    if (i < 2 * KCLUST * D / 4) {
        float4 v = ((const float4*)g_acc)[i];
        float* o = out + 1 + i * 4;
        o[0] = v.x; o[1] = v.y; o[2] = v.z; o[3] = v.w;
    }
}

// ---------------------------------------------------------------------------
extern "C" void kernel_launch(void* const* d_in, const int* in_sizes, int n_in,
                              void* d_out, int out_size) {
    const float* X  = (const float*)d_in[0];
    const float* SW = (const float*)d_in[1];
    const float* C  = (const float*)d_in[2];
    float* out = (float*)d_out;
    const int N = in_sizes[0] / D;

    cudaFuncSetAttribute(assign_kernel,
                         cudaFuncAttributeMaxDynamicSharedMemorySize, SMEM_TOTAL);

    prep_kernel<<<256, 256>>>(C, out, out_size);
    assign_kernel<<<N / BM, NT, SMEM_TOTAL>>>(X);
    rescore_scatter<<<N / 8, 256>>>(X, SW, C, out);
    finalize_kernel<<<(2 * KCLUST * D / 4 + 255) / 256, 256>>>(out);
}

// round 16
// speedup vs baseline: 4.3669x; 1.2853x over previous
#include <cuda_runtime.h>
#include <cuda_bf16.h>
#include <math.h>
#include <stdint.h>

#define D       128
#define KCLUST  1024
#define BM      128        // points per CTA
#define NSTAGE  8          // 8 x 128 clusters
#define NT      256
#define MAXN    262144

// smem layout (bytes)
#define SM_B0     0          // B stage buffer 0 (32KB)
#define SM_B1     32768      // B stage buffer 1 (32KB)
#define SM_RAW    65536      // raw X tile fp32  (64KB)
#define SM_CCOFF  131072     // CC (4KB)
#define SMEM_TOTAL (SM_CCOFF + KCLUST * 4)

#define B_STAGE_BYTES 32768

__device__ float g_CC[KCLUST];
// B bf16 fragments: [stage][ks 0..7][nf 0..15][lane 0..31] x uint2 {b0,b1}
__device__ __align__(16) uint2 g_Bperm[NSTAGE * 8 * 16 * 32];
__device__ int g_top1[MAXN];
__device__ int g_top2[MAXN];
// 16B-aligned scatter accumulator: [w_sum(K*D) | xw_sum(K*D)]
__device__ __align__(16) float g_acc[2 * KCLUST * D];

// ---------------------------------------------------------------------------
__device__ __forceinline__ uint32_t pack_bf16x2(float lo, float hi) {
    __nv_bfloat162 v = __floats2bfloat162_rn(lo, hi);   // x=lo -> low 16 bits
    return *(uint32_t*)&v;
}
__device__ __forceinline__ uint32_t smem_u32(const void* p) {
    return (uint32_t)__cvta_generic_to_shared(p);
}
__device__ __forceinline__ void cp_async16(uint32_t dst, const void* src) {
    asm volatile("cp.async.cg.shared.global [%0], [%1], 16;" :: "r"(dst), "l"(src));
}
#define CP_COMMIT() asm volatile("cp.async.commit_group;" ::: "memory")
#define CP_WAIT(n)  asm volatile("cp.async.wait_group %0;" :: "n"(n) : "memory")

__device__ __forceinline__ void mma_bf16(float* c, const uint4& a,
                                         uint32_t b0, uint32_t b1) {
    asm volatile(
        "mma.sync.aligned.m16n8k16.row.col.f32.bf16.bf16.f32 "
        "{%0,%1,%2,%3}, {%4,%5,%6,%7}, {%8,%9}, {%0,%1,%2,%3};"
        : "+f"(c[0]), "+f"(c[1]), "+f"(c[2]), "+f"(c[3])
        : "r"(a.x), "r"(a.y), "r"(a.z), "r"(a.w), "r"(b0), "r"(b1));
}

// Vector fp32 reduction to global (16B-aligned destination required)
__device__ __forceinline__ void red_add_v4(float* gptr, float4 v) {
    asm volatile("red.global.add.v4.f32 [%0], {%1, %2, %3, %4};"
                 :: "l"(gptr), "f"(v.x), "f"(v.y), "f"(v.z), "f"(v.w)
                 : "memory");
}

// ---------------------------------------------------------------------------
// Prep: zero output + scratch accumulator; CC[k]; build bf16 g_Bperm.
// ---------------------------------------------------------------------------
__global__ void prep_kernel(const float* __restrict__ C,
                            float* __restrict__ out, int total_out) {
    int tid  = blockIdx.x * blockDim.x + threadIdx.x;
    int nthr = gridDim.x * blockDim.x;
    for (int i = tid; i < total_out; i += nthr) out[i] = 0.0f;
    for (int i = tid; i < 2 * KCLUST * D / 4; i += nthr)
        ((float4*)g_acc)[i] = make_float4(0.f, 0.f, 0.f, 0.f);

    int warp = tid >> 5;
    int lane = tid & 31;
    if (warp < KCLUST) {
        const float4* row = (const float4*)(C + (size_t)warp * D);
        float4 v = row[lane];
        float s = v.x * v.x + v.y * v.y + v.z * v.z + v.w * v.w;
        #pragma unroll
        for (int o = 16; o > 0; o >>= 1) s += __shfl_xor_sync(0xffffffffu, s, o);
        if (lane == 0) g_CC[warp] = s;
    }

    // e: [stage(3b) | ks(3b) | nf(4b) | lane(5b)]  -> 32768 uint2
    for (int e = tid; e < NSTAGE * 8 * 16 * 32; e += nthr) {
        int l  = e & 31;
        int nf = (e >> 5) & 15;
        int ks = (e >> 9) & 7;          // FIXED: was (e >> 8), overlapped nf bit 3
        int st = e >> 12;               // FIXED: was (e >> 11)
        int cl = st * 128 + nf * 8 + (l >> 2);
        int k0 = ks * 16 + (l & 3) * 2;
        const float* cr = C + (size_t)cl * D;
        uint2 v;
        v.x = pack_bf16x2(cr[k0],     cr[k0 + 1]);      // k rows k0, k0+1
        v.y = pack_bf16x2(cr[k0 + 8], cr[k0 + 9]);      // k rows k0+8, k0+9
        g_Bperm[e] = v;
    }
}

// ---------------------------------------------------------------------------
// Assign: bf16 mma.sync m16n8k16, CTA = 128 points x 1024 clusters (8 stages).
// Warp grid 4x2 (warp tile 32x64); A fragments in registers for the whole
// kernel; per-stage smem traffic is B-only. Top-2 epilogue; exact rescore later.
// ---------------------------------------------------------------------------
__global__ __launch_bounds__(NT, 1)
void assign_kernel(const float* __restrict__ X) {
    extern __shared__ char smem[];
    const uint32_t sbase = smem_u32(smem);
    const int tid  = threadIdx.x;
    const int lane = tid & 31;
    const int wid  = tid >> 5;
    const int rg   = wid >> 1;       // row-group (0..3), 32 rows each
    const int cg   = wid & 1;        // col-group (0..1), 64 cols each
    const int n0   = blockIdx.x * BM;
    float* cc_s = (float*)(smem + SM_CCOFF);

    // ---- stage raw X tile (fp32, coalesced float4) ----
    {
        float4* raw = (float4*)(smem + SM_RAW);
        #pragma unroll
        for (int j = 0; j < 16; j++) {
            int idx = tid + j * NT;            // 4096 float4
            int row = idx >> 5, c4 = idx & 31;
            raw[idx] = ((const float4*)(X + (size_t)(n0 + row) * D))[c4];
        }
    }
    for (int i = tid; i < KCLUST; i += NT) cc_s[i] = g_CC[i];
    __syncthreads();

    // ---- build this warp's A fragments in registers (one-time) ----
    uint4 av[2][8];
    {
        const float* raw = (const float*)(smem + SM_RAW);
        #pragma unroll
        for (int ks = 0; ks < 8; ks++)
            #pragma unroll
            for (int mf = 0; mf < 2; mf++) {
                int row = rg * 32 + mf * 16 + (lane >> 2);
                int k0  = ks * 16 + (lane & 3) * 2;
                float2 p00 = *(const float2*)(raw + row * D + k0);
                float2 p10 = *(const float2*)(raw + (row + 8) * D + k0);
                float2 p01 = *(const float2*)(raw + row * D + k0 + 8);
                float2 p11 = *(const float2*)(raw + (row + 8) * D + k0 + 8);
                av[mf][ks].x = pack_bf16x2(p00.x, p00.y);
                av[mf][ks].y = pack_bf16x2(p10.x, p10.y);
                av[mf][ks].z = pack_bf16x2(p01.x, p01.y);
                av[mf][ks].w = pack_bf16x2(p11.x, p11.y);
            }
    }

    // ---- prefetch stage 0 into SM_B0 ----
    {
        const char* src = (const char*)g_Bperm;
        #pragma unroll
        for (int j = 0; j < 8; j++) {
            int c = tid + j * NT;              // 2048 x 16B
            cp_async16(sbase + SM_B0 + c * 16, src + (size_t)c * 16);
        }
        CP_COMMIT();
    }

    // persistent top-2 per owned row (4 rows: mf*2 + h)
    float tb1[4], tb2[4];
    int   ti1[4], ti2[4];
    #pragma unroll
    for (int i = 0; i < 4; i++) { tb1[i] = 3.4e38f; tb2[i] = 3.4e38f; ti1[i] = 0; ti2[i] = 1; }

    for (int s = 0; s < NSTAGE; s++) {
        // prefetch next stage
        if (s + 1 < NSTAGE) {
            uint32_t bb = sbase + (((s + 1) & 1) ? SM_B1 : SM_B0);
            const char* src = (const char*)g_Bperm + (size_t)(s + 1) * B_STAGE_BYTES;
            #pragma unroll
            for (int j = 0; j < 8; j++) {
                int c = tid + j * NT;
                cp_async16(bb + c * 16, src + (size_t)c * 16);
            }
            CP_COMMIT();
            CP_WAIT(1);
        } else {
            CP_WAIT(0);
        }
        __syncthreads();

        const uint2* Bb = (const uint2*)(smem + ((s & 1) ? SM_B1 : SM_B0));

        float acc[2][8][4];
        #pragma unroll
        for (int mf = 0; mf < 2; mf++)
            #pragma unroll
            for (int nf = 0; nf < 8; nf++)
                #pragma unroll
                for (int r = 0; r < 4; r++) acc[mf][nf][r] = 0.0f;

        #pragma unroll
        for (int ks = 0; ks < 8; ks++) {
            uint2 bv[8];
            #pragma unroll
            for (int nf = 0; nf < 8; nf++)
                bv[nf] = Bb[(ks * 16 + cg * 8 + nf) * 32 + lane];
            #pragma unroll
            for (int nf = 0; nf < 8; nf++)
                #pragma unroll
                for (int mf = 0; mf < 2; mf++)
                    mma_bf16(acc[mf][nf], av[mf][ks], bv[nf].x, bv[nf].y);
        }

        // fold tile into top-2:  m = CC - 2*dot
        #pragma unroll
        for (int nf = 0; nf < 8; nf++) {
            int colb = s * 128 + cg * 64 + nf * 8 + 2 * (lane & 3);
            float cc0 = cc_s[colb], cc1 = cc_s[colb + 1];
            #pragma unroll
            for (int mf = 0; mf < 2; mf++) {
                #pragma unroll
                for (int h = 0; h < 2; h++) {
                    int r = mf * 2 + h;
                    float m0 = fmaf(-2.0f, acc[mf][nf][h * 2 + 0], cc0);
                    float m1 = fmaf(-2.0f, acc[mf][nf][h * 2 + 1], cc1);
                    if (m0 < tb1[r]) { tb2[r] = tb1[r]; ti2[r] = ti1[r]; tb1[r] = m0; ti1[r] = colb; }
                    else if (m0 < tb2[r]) { tb2[r] = m0; ti2[r] = colb; }
                    if (m1 < tb1[r]) { tb2[r] = tb1[r]; ti2[r] = ti1[r]; tb1[r] = m1; ti1[r] = colb + 1; }
                    else if (m1 < tb2[r]) { tb2[r] = m1; ti2[r] = colb + 1; }
                }
            }
        }
        __syncthreads();   // buffer reuse guard
    }

    // ---- cross-warp merge (B buffers now dead) ----
    float4* red = (float4*)(smem + SM_B0);   // [row 0..127][cand 0..7]
    #pragma unroll
    for (int mf = 0; mf < 2; mf++)
        #pragma unroll
        for (int h = 0; h < 2; h++) {
            int r   = mf * 2 + h;
            int row = rg * 32 + mf * 16 + h * 8 + (lane >> 2);
            red[row * 8 + cg * 4 + (lane & 3)] =
                make_float4(tb1[r], tb2[r], __int_as_float(ti1[r]), __int_as_float(ti2[r]));
        }
    __syncthreads();

    if (tid < BM) {
        float b1 = 3.4e38f, b2 = 3.4e38f;
        int   i1 = 0,       i2 = 1;
        #pragma unroll
        for (int c = 0; c < 8; c++) {
            float4 v = red[tid * 8 + c];
            float cb1 = v.x, cb2 = v.y;
            int   ci1 = __float_as_int(v.z), ci2 = __float_as_int(v.w);
            if (cb1 < b1) { b2 = b1; i2 = i1; b1 = cb1; i1 = ci1; }
            else if (cb1 < b2) { b2 = cb1; i2 = ci1; }
            if (cb2 < b2) { b2 = cb2; i2 = ci2; }
        }
        g_top1[n0 + tid] = i1;
        g_top2[n0 + tid] = i2;
    }
}

// ---------------------------------------------------------------------------
// Rescore + scatter: one warp per point; exact fp32 d^2 for both candidates,
// pick winner, inertia, then 2 x red.global.add.v4.f32 into aligned scratch.
// ---------------------------------------------------------------------------
__global__ __launch_bounds__(256)
void rescore_scatter(const float* __restrict__ X,
                     const float* __restrict__ SW,
                     const float* __restrict__ C,
                     float* __restrict__ out) {
    __shared__ float sred[8];
    const int wid  = threadIdx.x >> 5;
    const int lane = threadIdx.x & 31;
    const int p    = blockIdx.x * 8 + wid;

    int i1 = g_top1[p];
    int i2 = g_top2[p];

    float4 x  = ((const float4*)(X  + (size_t)p  * D))[lane];
    float4 s  = ((const float4*)(SW + (size_t)p  * D))[lane];
    float4 c1 = ((const float4*)(C  + (size_t)i1 * D))[lane];
    float4 c2 = ((const float4*)(C  + (size_t)i2 * D))[lane];

    float dx, d1 = 0.0f, d2 = 0.0f;
    dx = x.x - c1.x; d1 += dx * dx;  dx = x.y - c1.y; d1 += dx * dx;
    dx = x.z - c1.z; d1 += dx * dx;  dx = x.w - c1.w; d1 += dx * dx;
    dx = x.x - c2.x; d2 += dx * dx;  dx = x.y - c2.y; d2 += dx * dx;
    dx = x.z - c2.z; d2 += dx * dx;  dx = x.w - c2.w; d2 += dx * dx;
    #pragma unroll
    for (int o = 16; o > 0; o >>= 1) {
        d1 += __shfl_xor_sync(0xffffffffu, d1, o);
        d2 += __shfl_xor_sync(0xffffffffu, d2, o);
    }

    bool take1 = (d1 < d2) || (d1 == d2 && i1 < i2);
    int   y    = take1 ? i1 : i2;
    float dmin = take1 ? d1 : d2;
    if (lane == 0) sred[wid] = sqrtf(fmaxf(dmin, 0.0f));

    float* wd = g_acc + (size_t)y * D + lane * 4;
    float* xd = g_acc + (size_t)KCLUST * D + (size_t)y * D + lane * 4;
    red_add_v4(wd, s);
    red_add_v4(xd, make_float4(x.x * s.x, x.y * s.y, x.z * s.z, x.w * s.w));

    __syncthreads();
    if (threadIdx.x == 0) {
        float acc = 0.0f;
        #pragma unroll
        for (int i = 0; i < 8; i++) acc += sred[i];
        atomicAdd(out, acc);
    }
}

// ---------------------------------------------------------------------------
// Tail: copy scratch accumulator into the (misaligned-by-1) output region.
// ---------------------------------------------------------------------------
__global__ void finalize_kernel(float* __restrict__ out) {
    int i = blockIdx.x * blockDim.x + threadIdx.x;
    if (i < 2 * KCLUST * D / 4) {
        float4 v = ((const float4*)g_acc)[i];
        float* o = out + 1 + i * 4;
        o[0] = v.x; o[1] = v.y; o[2] = v.z; o[3] = v.w;
    }
}

// ---------------------------------------------------------------------------
extern "C" void kernel_launch(void* const* d_in, const int* in_sizes, int n_in,
                              void* d_out, int out_size) {
    const float* X  = (const float*)d_in[0];
    const float* SW = (const float*)d_in[1];
    const float* C  = (const float*)d_in[2];
    float* out = (float*)d_out;
    const int N = in_sizes[0] / D;

    cudaFuncSetAttribute(assign_kernel,
                         cudaFuncAttributeMaxDynamicSharedMemorySize, SMEM_TOTAL);

    prep_kernel<<<256, 256>>>(C, out, out_size);
    assign_kernel<<<N / BM, NT, SMEM_TOTAL>>>(X);
    rescore_scatter<<<N / 8, 256>>>(X, SW, C, out);
    finalize_kernel<<<(2 * KCLUST * D / 4 + 255) / 256, 256>>>(out);
}